// round 9
// baseline (speedup 1.0000x reference)
#include <cuda_runtime.h>
#include <math.h>

#define BB   128
#define LL   1024
#define HSZ  512

typedef unsigned long long ull;

__device__ float g_t0[(size_t)BB * 32 * LL];      // [B,32,L] transposed input
__device__ float g_y [(size_t)BB * 256 * LL];     // conv raw out (<=256 ch)
__device__ float g_a [(size_t)BB * 64  * LL];     // activated conv (<=64 ch)
__device__ float g_X [(size_t)BB * LL * 256];     // conv stack out [B,L,256]
__device__ float g_scale[256];
__device__ float g_shift[256];
__device__ float g_h[3][BB * HSZ];                // 3-buffer rotation
__device__ float g_c[BB * HSZ];
__device__ int   g_bar_count;
__device__ int   g_bar_sense;

__global__ void zero_state_k() {
    int i = blockIdx.x * 256 + threadIdx.x;
    if (i < BB * HSZ) { g_h[0][i] = 0.f; g_c[i] = 0.f; }
    if (i == 0) { g_bar_count = 0; g_bar_sense = 0; }
}

__global__ void transpose_in_k(const float* __restrict__ xin) {
    int idx = blockIdx.x * 256 + threadIdx.x;      // B*L*32, c fastest
    if (idx >= BB * LL * 32) return;
    int c = idx & 31;
    int bl = idx >> 5;
    int l = bl & (LL - 1);
    int b = bl >> 10;
    g_t0[((size_t)b * 32 + c) * LL + l] = xin[idx];
}

// conv1d K=7 pad=3 stride=1, [B,C,L]. grid(L/256, B, Cout/8), 128 thr.
template<int CIN>
__global__ __launch_bounds__(128) void conv1d_k(const float* __restrict__ in,
                                                const float* __restrict__ w,
                                                int Cout) {
    const int l0 = blockIdx.x * 256, b = blockIdx.y, co0 = blockIdx.z * 8;
    __shared__ float xs[32][264];
    __shared__ float ws[8][32][8];
    float acc[8][2];
#pragma unroll
    for (int i = 0; i < 8; i++) { acc[i][0] = 0.f; acc[i][1] = 0.f; }

    for (int cb = 0; cb < CIN; cb += 32) {
        __syncthreads();
        for (int e = threadIdx.x; e < 32 * 262; e += 128) {
            int ci = e / 262, jj = e - ci * 262;
            int l = l0 - 3 + jj;
            xs[ci][jj] = (l >= 0 && l < LL) ? in[((size_t)b * CIN + cb + ci) * LL + l] : 0.f;
        }
        for (int e = threadIdx.x; e < 8 * 32 * 7; e += 128) {
            int co = e / 224, r = e - co * 224;
            int ci = r / 7, k = r - ci * 7;
            ws[co][ci][k] = w[((size_t)(co0 + co) * CIN + cb + ci) * 7 + k];
        }
        __syncthreads();
        const int lt = threadIdx.x;
        for (int ci = 0; ci < 32; ci++) {
#pragma unroll
            for (int k = 0; k < 7; k++) {
                float x0 = xs[ci][lt + k];
                float x1 = xs[ci][lt + 128 + k];
#pragma unroll
                for (int co = 0; co < 8; co++) {
                    float wv = ws[co][ci][k];
                    acc[co][0] = fmaf(x0, wv, acc[co][0]);
                    acc[co][1] = fmaf(x1, wv, acc[co][1]);
                }
            }
        }
    }
#pragma unroll
    for (int co = 0; co < 8; co++) {
        g_y[((size_t)b * Cout + co0 + co) * LL + l0 + threadIdx.x]       = acc[co][0];
        g_y[((size_t)b * Cout + co0 + co) * LL + l0 + 128 + threadIdx.x] = acc[co][1];
    }
}

__global__ void bn_stats_k(const float* __restrict__ gam,
                           const float* __restrict__ bet, int C) {
    int c = blockIdx.x;
    float s = 0.f, s2 = 0.f;
    for (int i = threadIdx.x; i < BB * LL; i += 256) {
        float v = g_y[((size_t)(i >> 10) * C + c) * LL + (i & (LL - 1))];
        s += v; s2 += v * v;
    }
    __shared__ float rs[256], rq[256];
    rs[threadIdx.x] = s; rq[threadIdx.x] = s2;
    __syncthreads();
    for (int o = 128; o > 0; o >>= 1) {
        if (threadIdx.x < o) { rs[threadIdx.x] += rs[threadIdx.x + o]; rq[threadIdx.x] += rq[threadIdx.x + o]; }
        __syncthreads();
    }
    if (threadIdx.x == 0) {
        float inv = 1.f / (float)(BB * LL);
        float mean = rs[0] * inv;
        float var  = rq[0] * inv - mean * mean;
        float sc = gam[c] * rsqrtf(var + 1e-5f);
        g_scale[c] = sc;
        g_shift[c] = bet[c] - mean * sc;
    }
}

__global__ void bn_apply_k(float* __restrict__ outBCL, int C, int toBLC) {
    size_t idx = (size_t)blockIdx.x * 256 + threadIdx.x;
    if (idx >= (size_t)BB * C * LL) return;
    int l = (int)(idx & (LL - 1));
    size_t bc = idx >> 10;
    int c = (int)(bc % C);
    int b = (int)(bc / C);
    float v = fmaxf(g_y[idx] * g_scale[c] + g_shift[c], 0.f);
    if (toBLC) g_X[((size_t)b * LL + l) * 256 + c] = v;
    else       outBCL[idx] = v;
}

// ---------------------------------------------------------------------------
// Persistent LSTM sequence kernel. grid (32,4) = 128 CTAs, 128 threads.
// CTA tile: 32 rows (batch) x 64 gate cols (= 16 h-cols x 4 gates), K=768.
// Weight tile (and decoder proj tile) resident in SMEM for all 1024 steps.
// Inner product via fma.rn.f32x2 (2 fp32 MACs / instr). Grid barrier per step.
// ---------------------------------------------------------------------------
template<bool PROJ>
__global__ __launch_bounds__(128) void lstm_seq_k(
    int hbase,
    const float* __restrict__ Wih, const float* __restrict__ Whh,
    const float* __restrict__ bih, const float* __restrict__ bhh,
    const float* __restrict__ outW, const float* __restrict__ outb,
    float* __restrict__ outBuf)
{
    extern __shared__ float smf[];
    float* Bsw = smf;                    // [768][64]  weight tile (B)
    float* Asb = smf + 768 * 64;         // [2][32][36] A double buffer
    float* gb  = Asb + 2304;             // [64] pre-added bias (i,f,g,o x 16)
    float* Pw  = gb + 64;                // [512][8]  proj weights (PROJ)
    float* ob  = Pw + 4096;              // [8]       proj bias   (PROJ)
    float (*Gs)[68] = (float(*)[68])Asb; // gates staging (reuses A buffers)

    const int tid = threadIdx.x;
    const int bx = blockIdx.x, by = blockIdx.y;
    const int n0 = bx * 16, m0 = by * 32;
    const int tx = tid & 15, ty = tid >> 4;

    // ---- one-time fills ----
    for (int e = tid * 4; e < 768 * 64; e += 512) {
        int col = e / 768, k = e % 768;
        int jr = (col >> 4) * HSZ + n0 + (col & 15);
        float4 w = (k < 256) ? *(const float4*)(Wih + (size_t)jr * 256 + k)
                             : *(const float4*)(Whh + (size_t)jr * HSZ + (k - 256));
        Bsw[(k + 0) * 64 + col] = w.x;
        Bsw[(k + 1) * 64 + col] = w.y;
        Bsw[(k + 2) * 64 + col] = w.z;
        Bsw[(k + 3) * 64 + col] = w.w;
    }
    if (tid < 64)
        gb[tid] = bih[(tid >> 4) * HSZ + n0 + (tid & 15)]
                + bhh[(tid >> 4) * HSZ + n0 + (tid & 15)];
    if constexpr (PROJ) {
        for (int e = tid; e < 4096; e += 128) {
            int q = e >> 9, k = e & 511;
            Pw[k * 8 + q] = outW[(size_t)(bx * 8 + q) * HSZ + k];
        }
        if (tid < 8) ob[tid] = outb[bx * 8 + tid];
    }
    __syncthreads();

    float ra[8];
    auto LOADA = [&](int kb, int t, const float* hin) {
        const int kbase = kb * 32;
#pragma unroll
        for (int j = 0; j < 8; j++) {
            int e = tid + j * 128;
            int row = e >> 5, kk = e & 31, k = kbase + kk;
            ra[j] = (k < 256)
                ? g_X[((size_t)(m0 + row) * LL + t) * 256 + k]
                : __ldcg(hin + (m0 + row) * HSZ + (k - 256));
        }
    };
    auto STOREA = [&](int pb) {
#pragma unroll
        for (int j = 0; j < 8; j++) {
            int e = tid + j * 128;
            Asb[pb * 1152 + (e >> 5) * 36 + (e & 31)] = ra[j];
        }
    };

    int ls = 0;
    LOADA(0, PROJ ? (LL - 1) : 0, g_h[hbase]);   // kb0 is pure-x; hin unused
    for (int s = 0; s < LL; s++) {
        const int t = PROJ ? (LL - 1 - s) : s;
        const float* hin = g_h[(hbase + s) % 3];
        float* hout      = g_h[(hbase + s + 1) % 3];

        STOREA(0);
        ull acc2[4][2];
#pragma unroll
        for (int r = 0; r < 4; r++) { acc2[r][0] = 0ull; acc2[r][1] = 0ull; }
        float pa0 = 0.f, pa1 = 0.f;
        int p = 0;

        for (int kb = 0; kb < 24; kb++) {
            __syncthreads();
            if (kb < 23) LOADA(kb + 1, t, hin);

            if (PROJ && kb >= 8) {
                const int prow = tid >> 3, q = tid & 7;
                const float* Pk = Pw + (kb - 8) * 256;
                const float* Ar = Asb + p * 1152;
#pragma unroll 8
                for (int kk = 0; kk < 32; kk++) {
                    float w0 = Pk[kk * 8 + q];
                    pa0 = fmaf(Ar[prow * 36 + kk],        w0, pa0);
                    pa1 = fmaf(Ar[(prow + 16) * 36 + kk], w0, pa1);
                }
            }
            {
                const float* Ar = Asb + p * 1152;
#pragma unroll
                for (int k4 = 0; k4 < 32; k4 += 4) {
                    float4 av0 = *(const float4*)(Ar + (ty * 4 + 0) * 36 + k4);
                    float4 av1 = *(const float4*)(Ar + (ty * 4 + 1) * 36 + k4);
                    float4 av2 = *(const float4*)(Ar + (ty * 4 + 2) * 36 + k4);
                    float4 av3 = *(const float4*)(Ar + (ty * 4 + 3) * 36 + k4);
#pragma unroll
                    for (int u = 0; u < 4; u++) {
                        ulonglong2 bv = *(const ulonglong2*)(Bsw + (size_t)(kb * 32 + k4 + u) * 64 + tx * 4);
#define FMA2R(AV, R) {                                                          \
    float a_ = (u == 0 ? (AV).x : u == 1 ? (AV).y : u == 2 ? (AV).z : (AV).w);  \
    ull pa_;                                                                    \
    asm("mov.b64 %0, {%1, %1};" : "=l"(pa_) : "f"(a_));                         \
    asm("fma.rn.f32x2 %0, %1, %2, %0;" : "+l"(acc2[R][0]) : "l"(pa_), "l"(bv.x)); \
    asm("fma.rn.f32x2 %0, %1, %2, %0;" : "+l"(acc2[R][1]) : "l"(pa_), "l"(bv.y)); }
                        FMA2R(av0, 0); FMA2R(av1, 1); FMA2R(av2, 2); FMA2R(av3, 3);
#undef FMA2R
                    }
                }
            }
            if (kb < 23) STOREA(p ^ 1);
            p ^= 1;
        }

        // stage gates (reuses A smem) and apply the cell
        __syncthreads();
#pragma unroll
        for (int r = 0; r < 4; r++) {
            float lo0, hi0, lo1, hi1;
            asm("mov.b64 {%0, %1}, %2;" : "=f"(lo0), "=f"(hi0) : "l"(acc2[r][0]));
            asm("mov.b64 {%0, %1}, %2;" : "=f"(lo1), "=f"(hi1) : "l"(acc2[r][1]));
            Gs[ty * 4 + r][tx * 4 + 0] = lo0;
            Gs[ty * 4 + r][tx * 4 + 1] = hi0;
            Gs[ty * 4 + r][tx * 4 + 2] = lo1;
            Gs[ty * 4 + r][tx * 4 + 3] = hi1;
        }
        __syncthreads();

#pragma unroll
        for (int rr = 0; rr < 4; rr++) {
            int e = tid + rr * 128;
            int row = e >> 4, nn = e & 15;
            int j = n0 + nn;
            float gi = Gs[row][nn]      + gb[nn];
            float gf = Gs[row][16 + nn] + gb[16 + nn];
            float gg = Gs[row][32 + nn] + gb[32 + nn];
            float go = Gs[row][48 + nn] + gb[48 + nn];
            float iv = 1.f / (1.f + expf(-gi));
            float fv = 1.f / (1.f + expf(-gf));
            float gv = tanhf(gg);
            float ov = 1.f / (1.f + expf(-go));
            int ci = (m0 + row) * HSZ + j;
            float cn = fv * g_c[ci] + iv * gv;
            g_c[ci] = cn;
            hout[ci] = ov * tanhf(cn);
        }

        if constexpr (PROJ) {
            const int prow = tid >> 3, q = tid & 7;
            float bo = ob[q];
            outBuf[((size_t)(m0 + prow) * LL + t) * 256 + bx * 8 + q]      = pa0 + bo;
            outBuf[((size_t)(m0 + prow + 16) * LL + t) * 256 + bx * 8 + q] = pa1 + bo;
        }

        // ---- grid barrier (sense-reversing); prefetch next x-chunk under it ----
        __threadfence();
        __syncthreads();
        bool lastArr = false;
        if (tid == 0) lastArr = (atomicAdd(&g_bar_count, 1) == 127);
        if (tid == 0 && lastArr) {
            g_bar_count = 0;
            __threadfence();
            atomicExch(&g_bar_sense, ls ^ 1);
        }
        if (s < LL - 1) LOADA(0, PROJ ? (LL - 2 - s) : (s + 1), hin);  // pure x
        if (tid == 0 && !lastArr) {
            while (*((volatile int*)&g_bar_sense) != (ls ^ 1)) __nanosleep(64);
        }
        __syncthreads();
        ls ^= 1;
    }
}

// ---------------------------------------------------------------------------
extern "C" void kernel_launch(void* const* d_in, const int* in_sizes, int n_in,
                              void* d_out, int out_size) {
    const float* xin     = (const float*)d_in[0];
    const float* conv1_w = (const float*)d_in[1];
    const float* bn1_g   = (const float*)d_in[2];
    const float* bn1_b   = (const float*)d_in[3];
    const float* conv2_w = (const float*)d_in[4];
    const float* bn2_g   = (const float*)d_in[5];
    const float* bn2_b   = (const float*)d_in[6];
    const float* conv3_w = (const float*)d_in[7];
    const float* bn3_g   = (const float*)d_in[8];
    const float* bn3_b   = (const float*)d_in[9];
    const float* eWih0   = (const float*)d_in[10];
    const float* eWhh0   = (const float*)d_in[11];
    const float* ebih0   = (const float*)d_in[12];
    const float* ebhh0   = (const float*)d_in[13];
    // d_in[14..17] encoder layer-1: provably dead (never reaches the output)
    const float* dWih0   = (const float*)d_in[18];
    const float* dWhh0   = (const float*)d_in[19];
    const float* dbih0   = (const float*)d_in[20];
    const float* dbhh0   = (const float*)d_in[21];
    // d_in[22..25] decoder layer-1: provably dead
    const float* outW    = (const float*)d_in[26];
    const float* outb    = (const float*)d_in[27];
    float* out = (float*)d_out;

    void *pt0 = 0, *pa = 0;
    cudaGetSymbolAddress(&pt0, g_t0);
    cudaGetSymbolAddress(&pa,  g_a);

    const int ENC_SM = (768 * 64 + 2304 + 64) * 4;              // 206,080 B
    const int DEC_SM = (768 * 64 + 2304 + 64 + 4096 + 8) * 4;   // 222,496 B
    cudaFuncSetAttribute(lstm_seq_k<false>, cudaFuncAttributeMaxDynamicSharedMemorySize, ENC_SM);
    cudaFuncSetAttribute(lstm_seq_k<true>,  cudaFuncAttributeMaxDynamicSharedMemorySize, DEC_SM);

    zero_state_k<<<(BB * HSZ + 255) / 256, 256>>>();
    transpose_in_k<<<(BB * LL * 32 + 255) / 256, 256>>>(xin);

    // conv1: 32 -> 32
    conv1d_k<32><<<dim3(4, BB, 4), 128>>>((const float*)pt0, conv1_w, 32);
    bn_stats_k<<<32, 256>>>(bn1_g, bn1_b, 32);
    bn_apply_k<<<(int)(((size_t)BB * 32 * LL + 255) / 256), 256>>>((float*)pa, 32, 0);

    // conv2: 32 -> 64
    conv1d_k<32><<<dim3(4, BB, 8), 128>>>((const float*)pa, conv2_w, 64);
    bn_stats_k<<<64, 256>>>(bn2_g, bn2_b, 64);
    bn_apply_k<<<(int)(((size_t)BB * 64 * LL + 255) / 256), 256>>>((float*)pa, 64, 0);

    // conv3: 64 -> 256 (+ transpose to [B,L,256])
    conv1d_k<64><<<dim3(4, BB, 32), 128>>>((const float*)pa, conv3_w, 256);
    bn_stats_k<<<256, 256>>>(bn3_g, bn3_b, 256);
    bn_apply_k<<<(int)(((size_t)BB * 256 * LL + 255) / 256), 256>>>(nullptr, 256, 1);

    // encoder: 1024 steps inside one persistent kernel. h starts in g_h[0].
    lstm_seq_k<false><<<dim3(32, 4), 128, ENC_SM>>>(0, eWih0, eWhh0, ebih0, ebhh0,
                                                    nullptr, nullptr, nullptr);
    // after 1024 steps, h lives in g_h[1024 % 3] = g_h[1]
    lstm_seq_k<true><<<dim3(32, 4), 128, DEC_SM>>>(1, dWih0, dWhh0, dbih0, dbhh0,
                                                   outW, outb, out);
}